// round 10
// baseline (speedup 1.0000x reference)
#include <cuda_runtime.h>
#include <cuda_bf16.h>
#include <math.h>
#include <stdint.h>

// ---------------- problem constants ----------------
#define N_TOK   128
#define N_B     32
#define N_S     4
#define N_H     16
#define D_MODEL 2048
#define D_QL    1536
#define D_QB    3072
#define D_KVL   512
#define D_NOPE  128
#define D_ROPE  64
#define D_V     128
#define D_HD    192
#define T_MAX   8192
#define T_START 8188
#define KVPE    576
#define ATT_SCALE 0.07216878364870323f

#define BM 64
#define BN 128
#define BK 16
#define SR 24            // smem row stride (bf16) for 16-wide k tiles
#define BR 264           // smem row stride for attnout 256-col tiles
#define NSPLIT 16        // attnout token splits (raised for grouped launches)
#define BGRP 4           // batches per L2-resident group

typedef __nv_bfloat16 bf16;

// ---------------- static scratch ----------------
__device__ float g_t1[N_TOK * D_QL];
__device__ float g_q[N_TOK * D_QB];
__device__ float g_kvf[N_TOK * KVPE];
__device__ float g_kvnew[N_TOK * KVPE];
__device__ float g_qabs[N_B * 64 * KVPE];
__device__ bf16 g_qh[N_B * 64 * KVPE];
__device__ bf16 g_ql[N_B * 64 * KVPE];
__device__ bf16 g_Kh[(size_t)N_B * T_MAX * KVPE];
__device__ bf16 g_Kl[(size_t)N_B * T_MAX * KVPE];
__device__ bf16 g_Ph[(size_t)N_B * 64 * T_MAX];
__device__ bf16 g_Pl[(size_t)N_B * 64 * T_MAX];
__device__ float g_lp[N_B * 64 * 4 * 64];
__device__ float g_l[N_B * 64];
__device__ float g_part[(size_t)N_B * NSPLIT * 64 * D_KVL];
__device__ float g_attn[N_B * 64 * D_KVL];
__device__ float g_o[N_TOK * 2048];
__device__ float g_red[5000000];          // split-K partials (max 12*128*3072)

// ---------------- helpers ----------------
__device__ __forceinline__ uint32_t packbf2(bf16 a, bf16 b) {
    __nv_bfloat162 t = __halves2bfloat162(a, b);
    return *reinterpret_cast<uint32_t*>(&t);
}
__device__ __forceinline__ void split2(float a, float b, uint32_t& h, uint32_t& l) {
    bf16 ah = __float2bfloat16(a);
    bf16 bh = __float2bfloat16(b);
    bf16 al = __float2bfloat16(a - __bfloat162float(ah));
    bf16 bl = __float2bfloat16(b - __bfloat162float(bh));
    h = packbf2(ah, bh);
    l = packbf2(al, bl);
}
__device__ __forceinline__ void mma_bf16(float* c, const uint32_t* a, uint32_t b0, uint32_t b1) {
    asm volatile(
        "mma.sync.aligned.m16n8k16.row.col.f32.bf16.bf16.f32 "
        "{%0,%1,%2,%3}, {%4,%5,%6,%7}, {%8,%9}, {%0,%1,%2,%3};\n"
        : "+f"(c[0]), "+f"(c[1]), "+f"(c[2]), "+f"(c[3])
        : "r"(a[0]), "r"(a[1]), "r"(a[2]), "r"(a[3]), "r"(b0), "r"(b1));
}
__device__ __forceinline__ void cpa16(void* s, const void* g) {
    uint32_t sa = (uint32_t)__cvta_generic_to_shared(s);
    asm volatile("cp.async.cg.shared.global [%0], [%1], 16;\n" :: "r"(sa), "l"(g));
}
#define CP_COMMIT() asm volatile("cp.async.commit_group;\n")
#define CP_WAIT1()  asm volatile("cp.async.wait_group 1;\n")
#define CP_WAIT0()  asm volatile("cp.async.wait_group 0;\n")

__device__ __forceinline__ void ldsm4(uint32_t& r0, uint32_t& r1, uint32_t& r2, uint32_t& r3,
                                      const void* p) {
    uint32_t a = (uint32_t)__cvta_generic_to_shared(p);
    asm volatile("ldmatrix.sync.aligned.m8n8.x4.shared.b16 {%0,%1,%2,%3}, [%4];\n"
                 : "=r"(r0), "=r"(r1), "=r"(r2), "=r"(r3) : "r"(a));
}
__device__ __forceinline__ void ldsm4t(uint32_t& r0, uint32_t& r1, uint32_t& r2, uint32_t& r3,
                                       const void* p) {
    uint32_t a = (uint32_t)__cvta_generic_to_shared(p);
    asm volatile("ldmatrix.sync.aligned.m8n8.x4.trans.shared.b16 {%0,%1,%2,%3}, [%4];\n"
                 : "=r"(r0), "=r"(r1), "=r"(r2), "=r"(r3) : "r"(a));
}

// =======================================================================
// fp32 SGEMM NN body with K-range (for split-K). Tile 64x128, 256 thr.
// =======================================================================
__device__ __forceinline__ void sgemm_nn_body(
    const float* __restrict__ A, int lda,
    const float* __restrict__ B, int ldb,
    float* __restrict__ C, int ldc,
    int N, int kbeg, int kend)
{
    __shared__ float As[BK][BM];
    __shared__ float Bs[BK][BN];
    const int tid = threadIdx.x;
    const int tx = tid & 15, ty = tid >> 4;
    const int m0 = blockIdx.y * BM;
    const int n0 = blockIdx.x * BN;
    const int am = tid >> 2, ak = (tid & 3) << 2;
    const int bkr = tid >> 4, bn = (tid & 15) << 3;

    float acc[4][8];
#pragma unroll
    for (int i = 0; i < 4; i++)
#pragma unroll
        for (int j = 0; j < 8; j++) acc[i][j] = 0.f;

    for (int k0 = kbeg; k0 < kend; k0 += BK) {
        float4 av = *(const float4*)(A + (size_t)(m0 + am) * lda + k0 + ak);
        As[ak + 0][am] = av.x; As[ak + 1][am] = av.y;
        As[ak + 2][am] = av.z; As[ak + 3][am] = av.w;
        const float* bp = B + (size_t)(k0 + bkr) * ldb + n0 + bn;
        if (n0 + bn + 7 < N) {
            *(float4*)&Bs[bkr][bn]     = *(const float4*)bp;
            *(float4*)&Bs[bkr][bn + 4] = *(const float4*)(bp + 4);
        } else {
#pragma unroll
            for (int j = 0; j < 8; j++)
                Bs[bkr][bn + j] = (n0 + bn + j < N) ? bp[j] : 0.f;
        }
        __syncthreads();
#pragma unroll
        for (int kk = 0; kk < BK; kk++) {
            float a[4], bb[8];
            *(float4*)a      = *(const float4*)&As[kk][ty << 2];
            *(float4*)&bb[0] = *(const float4*)&Bs[kk][tx << 3];
            *(float4*)&bb[4] = *(const float4*)&Bs[kk][(tx << 3) + 4];
#pragma unroll
            for (int i = 0; i < 4; i++)
#pragma unroll
                for (int j = 0; j < 8; j++)
                    acc[i][j] = fmaf(a[i], bb[j], acc[i][j]);
        }
        __syncthreads();
    }
#pragma unroll
    for (int i = 0; i < 4; i++) {
        int m = m0 + (ty << 2) + i;
        float* cp = C + (size_t)m * ldc + n0 + (tx << 3);
#pragma unroll
        for (int j = 0; j < 8; j++)
            if (n0 + (tx << 3) + j < N) cp[j] = acc[i][j];
    }
}

// ---------------- split-K GEMM wrappers ----------------
__global__ void k_sgemm_xqa(const float* __restrict__ x, const float* __restrict__ w) {
    const int z = blockIdx.z, ks = D_MODEL / 16;
    sgemm_nn_body(x, D_MODEL, w, D_QL, g_red + (size_t)z * N_TOK * D_QL, D_QL,
                  D_QL, z * ks, (z + 1) * ks);
}
__global__ void k_sgemm_qb(const float* __restrict__ w) {
    const int z = blockIdx.z, ks = D_QL / 12;
    sgemm_nn_body(g_t1, D_QL, w, D_QB, g_red + (size_t)z * N_TOK * D_QB, D_QB,
                  D_QB, z * ks, (z + 1) * ks);
}
__global__ void k_sgemm_kva(const float* __restrict__ x, const float* __restrict__ w) {
    const int z = blockIdx.z, ks = D_MODEL / 16;
    sgemm_nn_body(x, D_MODEL, w, KVPE, g_red + (size_t)z * N_TOK * KVPE, KVPE,
                  KVPE, z * ks, (z + 1) * ks);
}
__global__ void k_sgemm_wo(const float* __restrict__ w) {
    const int z = blockIdx.z, ks = 2048 / 16;
    sgemm_nn_body(g_o, 2048, w, 2048, g_red + (size_t)z * N_TOK * 2048, 2048,
                  2048, z * ks, (z + 1) * ks);
}

// ---------------- reduce wrappers ----------------
__device__ __forceinline__ void reduce_body(const float* __restrict__ src,
                                            float* __restrict__ dst, int mn, int splits) {
    int i = blockIdx.x * 256 + threadIdx.x;
    if (i >= mn) return;
    float s = 0.f;
    for (int k = 0; k < splits; k++) s += src[i + (size_t)k * mn];
    dst[i] = s;
}
__global__ void k_red_t1()  { reduce_body(g_red, g_t1,  N_TOK * D_QL, 16); }
__global__ void k_red_q()   { reduce_body(g_red, g_q,   N_TOK * D_QB, 12); }
__global__ void k_red_kvf() { reduce_body(g_red, g_kvf, N_TOK * KVPE, 16); }
__global__ void k_red_o()   { reduce_body(g_red, g_o,   N_TOK * 2048, 4); }
__global__ void k_red_out(float* __restrict__ out) { reduce_body(g_red, out, N_TOK * 2048, 16); }

// =======================================================================
// RMSNorm q_lora rows (1536)
// =======================================================================
__global__ void k_rms_q(const float* __restrict__ w)
{
    const int m = blockIdx.x, tid = threadIdx.x;
    float* row = g_t1 + (size_t)m * D_QL;
    float s = 0.f;
    for (int i = tid; i < D_QL / 4; i += 256) {
        float4 v = ((const float4*)row)[i];
        s += v.x * v.x + v.y * v.y + v.z * v.z + v.w * v.w;
    }
    __shared__ float sd[256];
    sd[tid] = s; __syncthreads();
    for (int o = 128; o > 0; o >>= 1) {
        if (tid < o) sd[tid] += sd[tid + o];
        __syncthreads();
    }
    const float inv = rsqrtf(sd[0] / (float)D_QL + 1e-6f);
    for (int i = tid; i < D_QL / 4; i += 256) {
        float4 v = ((const float4*)row)[i];
        float4 wv = ((const float4*)w)[i];
        v.x *= inv * wv.x; v.y *= inv * wv.y;
        v.z *= inv * wv.z; v.w *= inv * wv.w;
        ((float4*)row)[i] = v;
    }
}

// =======================================================================
// KV prep for the 4 new tokens per batch
// =======================================================================
__global__ void k_kvprep(const float* __restrict__ kvw,
                         const float* __restrict__ fc,
                         const float* __restrict__ fs)
{
    const int m = blockIdx.x, tid = threadIdx.x;
    const float* row = g_kvf + (size_t)m * KVPE;
    float* out = g_kvnew + (size_t)m * KVPE;
    float4 v = ((const float4*)row)[tid];
    float s = v.x * v.x + v.y * v.y + v.z * v.z + v.w * v.w;
    __shared__ float sd[128];
    sd[tid] = s; __syncthreads();
    for (int o = 64; o > 0; o >>= 1) {
        if (tid < o) sd[tid] += sd[tid + o];
        __syncthreads();
    }
    const float inv = rsqrtf(sd[0] / (float)D_KVL + 1e-6f);
    out[tid * 4 + 0] = v.x * inv * kvw[tid * 4 + 0];
    out[tid * 4 + 1] = v.y * inv * kvw[tid * 4 + 1];
    out[tid * 4 + 2] = v.z * inv * kvw[tid * 4 + 2];
    out[tid * 4 + 3] = v.w * inv * kvw[tid * 4 + 3];
    if (tid < 32) {
        const int sidx = m & 3;
        const float c = fc[sidx * 32 + tid], sn = fs[sidx * 32 + tid];
        const float x0 = row[512 + 2 * tid], x1 = row[512 + 2 * tid + 1];
        out[512 + 2 * tid]     = x0 * c - x1 * sn;
        out[512 + 2 * tid + 1] = x0 * sn + x1 * c;
    }
}

// =======================================================================
// Pre-convert BGRP batches of the cache into bf16 hi/lo rows (grouped).
// =======================================================================
__global__ void k_cvt(const float* __restrict__ kvc, const float* __restrict__ pec,
                      int b0)
{
    const uint32_t g = blockIdx.x * 256 + threadIdx.x;
    if (g >= (uint32_t)BGRP * T_MAX * (KVPE / 8)) return;
    const uint32_t rl = g / (KVPE / 8);               // row within group
    const int seg = (g - rl * (KVPE / 8)) * 8;
    const int t = rl & (T_MAX - 1);
    const int b = b0 + (rl >> 13);
    const size_t row = (size_t)b * T_MAX + t;

    const float* src;
    if (t >= T_START)       src = g_kvnew + (size_t)((b << 2) + (t - T_START)) * KVPE + seg;
    else if (seg < D_KVL)   src = kvc + row * D_KVL + seg;
    else                    src = pec + row * D_ROPE + (seg - D_KVL);

    float4 v0 = *(const float4*)src;
    float4 v1 = *(const float4*)(src + 4);
    uint32_t h[4], l[4];
    split2(v0.x, v0.y, h[0], l[0]);
    split2(v0.z, v0.w, h[1], l[1]);
    split2(v1.x, v1.y, h[2], l[2]);
    split2(v1.z, v1.w, h[3], l[3]);
    *(uint4*)(g_Kh + row * KVPE + seg) = *(uint4*)h;
    *(uint4*)(g_Kl + row * KVPE + seg) = *(uint4*)l;
}

// =======================================================================
// Absorb q_nope through wkv_b[:, :128, :] -> g_qabs[:, :512]
// =======================================================================
__global__ void k_absorb(const float* __restrict__ wkvb)
{
    __shared__ float As[BK][BM];
    __shared__ float Bs[BK][BN];
    const int h = blockIdx.z, tid = threadIdx.x;
    const int tx = tid & 15, ty = tid >> 4;
    const int m0 = blockIdx.y * BM, n0 = blockIdx.x * BN;
    const int am = tid >> 2, ak = (tid & 3) << 2;
    const int bkr = tid >> 4, bn = (tid & 15) << 3;
    const float* A = g_q + h * D_HD;
    const float* B = wkvb + (size_t)(h * 256) * D_KVL;
    float acc[4][8];
#pragma unroll
    for (int i = 0; i < 4; i++)
#pragma unroll
        for (int j = 0; j < 8; j++) acc[i][j] = 0.f;
    for (int k0 = 0; k0 < D_NOPE; k0 += BK) {
        float4 av = *(const float4*)(A + (size_t)(m0 + am) * D_QB + k0 + ak);
        As[ak + 0][am] = av.x; As[ak + 1][am] = av.y;
        As[ak + 2][am] = av.z; As[ak + 3][am] = av.w;
        const float* bp = B + (size_t)(k0 + bkr) * D_KVL + n0 + bn;
        *(float4*)&Bs[bkr][bn]     = *(const float4*)bp;
        *(float4*)&Bs[bkr][bn + 4] = *(const float4*)(bp + 4);
        __syncthreads();
#pragma unroll
        for (int kk = 0; kk < BK; kk++) {
            float a[4], bb[8];
            *(float4*)a      = *(const float4*)&As[kk][ty << 2];
            *(float4*)&bb[0] = *(const float4*)&Bs[kk][tx << 3];
            *(float4*)&bb[4] = *(const float4*)&Bs[kk][(tx << 3) + 4];
#pragma unroll
            for (int i = 0; i < 4; i++)
#pragma unroll
                for (int j = 0; j < 8; j++)
                    acc[i][j] = fmaf(a[i], bb[j], acc[i][j]);
        }
        __syncthreads();
    }
#pragma unroll
    for (int i = 0; i < 4; i++) {
        const int m = m0 + (ty << 2) + i;
        const int row = (m >> 2) * 64 + h * 4 + (m & 3);
        float* cp = g_qabs + (size_t)row * KVPE + n0 + (tx << 3);
#pragma unroll
        for (int j = 0; j < 8; j++) cp[j] = acc[i][j];
    }
}

// =======================================================================
// Rope q_pe -> g_qabs[..., 512:576]
// =======================================================================
__global__ void k_qrope(const float* __restrict__ fc, const float* __restrict__ fs)
{
    const int idx = blockIdx.x * blockDim.x + threadIdx.x;
    const int j = idx & 31, h = (idx >> 5) & 15, m = idx >> 9, s = m & 3;
    const float c = fc[s * 32 + j], sn = fs[s * 32 + j];
    const float* src = g_q + (size_t)m * D_QB + h * D_HD + D_NOPE + 2 * j;
    const float x0 = src[0], x1 = src[1];
    const int row = (m >> 2) * 64 + h * 4 + s;
    float* dst = g_qabs + (size_t)row * KVPE + 512 + 2 * j;
    dst[0] = x0 * c - x1 * sn;
    dst[1] = x0 * sn + x1 * c;
}

// =======================================================================
// Split g_qabs fp32 -> bf16 hi/lo
// =======================================================================
__global__ void k_qsplit()
{
    const int i = blockIdx.x * 256 + threadIdx.x;
    if (i >= N_B * 64 * KVPE) return;
    float v = g_qabs[i];
    bf16 h = __float2bfloat16(v);
    g_qh[i] = h;
    g_ql[i] = __float2bfloat16(v - __bfloat162float(h));
}

// =======================================================================
// Scores: P = exp(scale * Q' KV^T). Grouped: b = b0 + blockIdx.y.
// =======================================================================
__global__ __launch_bounds__(256, 2) void k_scores2(int b0)
{
    __shared__ bf16 Qh[2][64 * SR], Ql[2][64 * SR];
    __shared__ bf16 Kh[2][128 * SR], Kl[2][128 * SR];

    const int tid = threadIdx.x;
    const int lane = tid & 31, w = tid >> 5;
    const int wm = w & 1, wt = w >> 1;
    const int b = b0 + blockIdx.y;
    const int tt = blockIdx.x;
    const int t0 = tt * 128;

    float acc[2][4][4];
#pragma unroll
    for (int mi = 0; mi < 2; mi++)
#pragma unroll
        for (int ni = 0; ni < 4; ni++)
#pragma unroll
            for (int q = 0; q < 4; q++) acc[mi][ni][q] = 0.f;

    const int srow = tid >> 1, shf = (tid & 1) * 8;
    const bf16* gqh = g_qh + ((size_t)b * 64 + (srow & 63)) * KVPE + shf;
    const bf16* gql = g_ql + ((size_t)b * 64 + (srow & 63)) * KVPE + shf;
    const bf16* gkh = g_Kh + ((size_t)b * T_MAX + t0 + srow) * KVPE + shf;
    const bf16* gkl = g_Kl + ((size_t)b * T_MAX + t0 + srow) * KVPE + shf;

#define SC_STAGE(c, buf) do {                                             \
        const int k0_ = (c) * 16;                                         \
        if (tid < 128) {                                                  \
            cpa16(&Qh[buf][srow * SR + shf], gqh + k0_);                  \
            cpa16(&Ql[buf][srow * SR + shf], gql + k0_);                  \
        }                                                                 \
        cpa16(&Kh[buf][srow * SR + shf], gkh + k0_);                      \
        cpa16(&Kl[buf][srow * SR + shf], gkl + k0_);                      \
        CP_COMMIT();                                                      \
    } while (0)

    const int lg = lane >> 3, lidx = lane & 7;
    const int lr = lane >> 2, lk = (lane & 3) * 2;

    SC_STAGE(0, 0);

    for (int c = 0; c < KVPE / 16; c++) {
        const int buf = c & 1;
        if (c + 1 < KVPE / 16) SC_STAGE(c + 1, (c + 1) & 1);
        if (c + 1 < KVPE / 16) { CP_WAIT1(); } else { CP_WAIT0(); }
        __syncthreads();

        uint32_t ah[2][4], al[2][4];
#pragma unroll
        for (int mi = 0; mi < 2; mi++) {
            const int arow = wm * 32 + mi * 16 + ((lg & 1) << 3) + lidx;
            const int acol = (lg >> 1) << 3;
            ldsm4(ah[mi][0], ah[mi][1], ah[mi][2], ah[mi][3], &Qh[buf][arow * SR + acol]);
            ldsm4(al[mi][0], al[mi][1], al[mi][2], al[mi][3], &Ql[buf][arow * SR + acol]);
        }
#pragma unroll
        for (int p = 0; p < 2; p++) {
            const int brow = wt * 32 + p * 16 + ((lg >> 1) << 3) + lidx;
            const int bcol = (lg & 1) << 3;
            uint32_t bh[4], bl[4];
            ldsm4(bh[0], bh[1], bh[2], bh[3], &Kh[buf][brow * SR + bcol]);
            ldsm4(bl[0], bl[1], bl[2], bl[3], &Kl[buf][brow * SR + bcol]);
#pragma unroll
            for (int mi = 0; mi < 2; mi++) {
                mma_bf16(acc[mi][2 * p],     ah[mi], bh[0], bh[1]);
                mma_bf16(acc[mi][2 * p],     ah[mi], bl[0], bl[1]);
                mma_bf16(acc[mi][2 * p],     al[mi], bh[0], bh[1]);
                mma_bf16(acc[mi][2 * p + 1], ah[mi], bh[2], bh[3]);
                mma_bf16(acc[mi][2 * p + 1], ah[mi], bl[2], bl[3]);
                mma_bf16(acc[mi][2 * p + 1], al[mi], bh[2], bh[3]);
            }
        }
        __syncthreads();
    }
#undef SC_STAGE

    float s0[2] = {0.f, 0.f}, s1[2] = {0.f, 0.f};
#pragma unroll
    for (int mi = 0; mi < 2; mi++) {
#pragma unroll
        for (int ni = 0; ni < 4; ni++) {
            const int r = wm * 32 + mi * 16 + lr;
            const int t = t0 + wt * 32 + ni * 8 + lk;
            size_t base = ((size_t)b * 64 + r) * T_MAX + t;
            float e0 = __expf(acc[mi][ni][0] * ATT_SCALE);
            float e1 = __expf(acc[mi][ni][1] * ATT_SCALE);
            float e2 = __expf(acc[mi][ni][2] * ATT_SCALE);
            float e3 = __expf(acc[mi][ni][3] * ATT_SCALE);
            s0[mi] += e0 + e1;
            s1[mi] += e2 + e3;
            uint32_t h, l;
            split2(e0, e1, h, l);
            *(uint32_t*)&g_Ph[base] = h;
            *(uint32_t*)&g_Pl[base] = l;
            split2(e2, e3, h, l);
            *(uint32_t*)&g_Ph[base + (size_t)8 * T_MAX] = h;
            *(uint32_t*)&g_Pl[base + (size_t)8 * T_MAX] = l;
        }
    }
#pragma unroll
    for (int mi = 0; mi < 2; mi++) {
        s0[mi] += __shfl_xor_sync(0xffffffffu, s0[mi], 1);
        s0[mi] += __shfl_xor_sync(0xffffffffu, s0[mi], 2);
        s1[mi] += __shfl_xor_sync(0xffffffffu, s1[mi], 1);
        s1[mi] += __shfl_xor_sync(0xffffffffu, s1[mi], 2);
        if ((lane & 3) == 0) {
            const int r = wm * 32 + mi * 16 + lr;
            float* dst = g_lp + ((size_t)(b * 64 + tt) * 4 + wt) * 64;
            dst[r]     = s0[mi];
            dst[r + 8] = s1[mi];
        }
    }
}

__global__ void k_lred()
{
    const int b = blockIdx.x, r = threadIdx.x;
    float s = 0.f;
    for (int i = 0; i < 256; i++)
        s += g_lp[((size_t)(b * 64 + (i >> 2)) * 4 + (i & 3)) * 64 + r];
    g_l[b * 64 + r] = s;
}

// =======================================================================
// Attention out: partial = P @ KV over token slice. Grouped: b = b0 + blockIdx.z.
// =======================================================================
__global__ __launch_bounds__(256, 2) void k_attnout2(int b0)
{
    __shared__ bf16 Ah[2][64 * SR], Al[2][64 * SR];
    __shared__ bf16 Bh[2][16 * BR], Bl[2][16 * BR];

    const int tid = threadIdx.x;
    const int lane = tid & 31, w = tid >> 5;
    const int wm = w & 1, wc = w >> 1;
    const int c0 = blockIdx.x * 256;
    const int split = blockIdx.y;
    const int b = b0 + blockIdx.z;

    float acc[2][8][4];
#pragma unroll
    for (int mi = 0; mi < 2; mi++)
#pragma unroll
        for (int ni = 0; ni < 8; ni++)
#pragma unroll
            for (int q = 0; q < 4; q++) acc[mi][ni][q] = 0.f;

    const int arow = tid >> 1, ahf = (tid & 1) * 8;
    const int bt = tid >> 4, bcs = (tid & 15) * 16;
    const int tbase = split * (T_MAX / NSPLIT);

    const bf16* gph = g_Ph + ((size_t)b * 64 + (arow & 63)) * T_MAX + tbase + ahf;
    const bf16* gpl = g_Pl + ((size_t)b * 64 + (arow & 63)) * T_MAX + tbase + ahf;
    const bf16* gbh = g_Kh + ((size_t)b * T_MAX + tbase + bt) * KVPE + c0 + bcs;
    const bf16* gbl = g_Kl + ((size_t)b * T_MAX + tbase + bt) * KVPE + c0 + bcs;

#define AO_STAGE(c, buf) do {                                              \
        const int tk_ = (c) * 16;                                          \
        if (tid < 128) {                                                   \
            cpa16(&Ah[buf][arow * SR + ahf], gph + tk_);                   \
            cpa16(&Al[buf][arow * SR + ahf], gpl + tk_);                   \
        }                                                                  \
        cpa16(&Bh[buf][bt * BR + bcs],     gbh + (size_t)tk_ * KVPE);      \
        cpa16(&Bh[buf][bt * BR + bcs + 8], gbh + (size_t)tk_ * KVPE + 8);  \
        cpa16(&Bl[buf][bt * BR + bcs],     gbl + (size_t)tk_ * KVPE);      \
        cpa16(&Bl[buf][bt * BR + bcs + 8], gbl + (size_t)tk_ * KVPE + 8);  \
        CP_COMMIT();                                                       \
    } while (0)

    const int lg = lane >> 3, lidx = lane & 7;
    const int lr = lane >> 2, lk = (lane & 3) * 2;
    const int NCH = (T_MAX / NSPLIT) / 16;

    AO_STAGE(0, 0);

    for (int c = 0; c < NCH; c++) {
        const int buf = c & 1;
        if (c + 1 < NCH) AO_STAGE(c + 1, (c + 1) & 1);
        if (c + 1 < NCH) { CP_WAIT1(); } else { CP_WAIT0(); }
        __syncthreads();

        uint32_t ah[2][4], al[2][4];
#pragma unroll
        for (int mi = 0; mi < 2; mi++) {
            const int r = wm * 32 + mi * 16 + ((lg & 1) << 3) + lidx;
            const int acol = (lg >> 1) << 3;
            ldsm4(ah[mi][0], ah[mi][1], ah[mi][2], ah[mi][3], &Ah[buf][r * SR + acol]);
            ldsm4(al[mi][0], al[mi][1], al[mi][2], al[mi][3], &Al[buf][r * SR + acol]);
        }
#pragma unroll
        for (int p = 0; p < 4; p++) {
            const int C = wc * 64 + p * 16;
            const int brow = ((lg & 1) << 3) + lidx;
            const int bcol = C + ((lg >> 1) << 3);
            uint32_t bh[4], bl[4];
            ldsm4t(bh[0], bh[1], bh[2], bh[3], &Bh[buf][brow * BR + bcol]);
            ldsm4t(bl[0], bl[1], bl[2], bl[3], &Bl[buf][brow * BR + bcol]);
#pragma unroll
            for (int mi = 0; mi < 2; mi++) {
                mma_bf16(acc[mi][2 * p],     ah[mi], bh[0], bh[1]);
                mma_bf16(acc[mi][2 * p],     ah[mi], bl[0], bl[1]);
                mma_bf16(acc[mi][2 * p],     al[mi], bh[0], bh[1]);
                mma_bf16(acc[mi][2 * p + 1], ah[mi], bh[2], bh[3]);
                mma_bf16(acc[mi][2 * p + 1], ah[mi], bl[2], bl[3]);
                mma_bf16(acc[mi][2 * p + 1], al[mi], bh[2], bh[3]);
            }
        }
        __syncthreads();
    }
#undef AO_STAGE

#pragma unroll
    for (int mi = 0; mi < 2; mi++) {
#pragma unroll
        for (int ni = 0; ni < 8; ni++) {
            const int r = wm * 32 + mi * 16 + lr;
            const int cc = c0 + wc * 64 + ni * 8 + lk;
            float* p = g_part + (((size_t)(b * NSPLIT + split) * 64 + r) * D_KVL + cc);
            *(float2*)p = make_float2(acc[mi][ni][0], acc[mi][ni][1]);
            *(float2*)(p + (size_t)8 * D_KVL) = make_float2(acc[mi][ni][2], acc[mi][ni][3]);
        }
    }
}

// =======================================================================
// Reduce attn partials over splits and normalize by l.
// =======================================================================
__global__ void k_attnred()
{
    const int i = blockIdx.x * 256 + threadIdx.x;
    if (i >= N_B * 64 * D_KVL) return;
    const int c = i & 511;
    const int r = (i >> 9) & 63;
    const int b = i >> 15;
    float s = 0.f;
#pragma unroll
    for (int k = 0; k < NSPLIT; k++)
        s += g_part[((size_t)(b * NSPLIT + k) * 64 + r) * D_KVL + c];
    g_attn[((size_t)b * 64 + r) * D_KVL + c] = s / g_l[b * 64 + r];
}

// =======================================================================
// V projection, split-K over c (512 -> 4 x 128). grid (4 kz, 2 mtile, 16 h).
// =======================================================================
__global__ void k_projv(const float* __restrict__ wkvb)
{
    __shared__ float As[BK][BM];
    __shared__ float Bs[BK][BN];
    const int h = blockIdx.z, tid = threadIdx.x;
    const int kz = blockIdx.x;
    const int tx = tid & 15, ty = tid >> 4;
    const int m0 = blockIdx.y * BM;
    const int am = tid >> 2, ak = (tid & 3) << 2;
    const int bt = tid >> 1, bkq = (tid & 1) << 3;

    const int lm = m0 + am;
    const int arowi = (lm >> 2) * 64 + h * 4 + (lm & 3);
    const float* arp = g_attn + (size_t)arowi * D_KVL;
    const float* brp = wkvb + (size_t)(h * 256 + 128 + bt) * D_KVL;

    float acc[4][8];
#pragma unroll
    for (int i = 0; i < 4; i++)
#pragma unroll
        for (int j = 0; j < 8; j++) acc[i][j] = 0.f;

    const int kbeg = kz * 128, kend = kbeg + 128;
    for (int k0 = kbeg; k0 < kend; k0 += BK) {
        float4 av = *(const float4*)(arp + k0 + ak);
        As[ak + 0][am] = av.x; As[ak + 1][am] = av.y;
        As[ak + 2][am] = av.z; As[ak + 3][am] = av.w;
        float4 b0 = *(const float4*)(brp + k0 + bkq);
        float4 b1 = *(const float4*)(brp + k0 + bkq + 4);
        Bs[bkq + 0][bt] = b0.x; Bs[bkq + 1][bt] = b0.y;
        Bs[bkq + 2][bt] = b0.z; Bs[bkq + 3][bt] = b0.w;
        Bs[bkq + 4][bt] = b1.x; Bs[bkq + 5][bt] = b1.y;
        Bs[bkq + 6][bt] = b1.z; Bs[bkq + 7][bt] = b1.w;
        __syncthreads();
#pragma unroll
        for (int kk = 0; kk < BK; kk++) {
            float a[4], bb[8];
            *(float4*)a      = *(const float4*)&As[kk][ty << 2];
            *(float4*)&bb[0] = *(const float4*)&Bs[kk][tx << 3];
            *(float4*)&bb[4] = *(const float4*)&Bs[kk][(tx << 3) + 4];
#pragma unroll
            for (int i = 0; i < 4; i++)
#pragma unroll
                for (int j = 0; j < 8; j++)
                    acc[i][j] = fmaf(a[i], bb[j], acc[i][j]);
        }
        __syncthreads();
    }
#pragma unroll
    for (int i = 0; i < 4; i++) {
        const int m = m0 + (ty << 2) + i;
        float* cp = g_red + (size_t)kz * N_TOK * 2048 + (size_t)m * 2048 + h * D_V + (tx << 3);
#pragma unroll
        for (int j = 0; j < 8; j++) cp[j] = acc[i][j];
    }
}

// =======================================================================
// launch
// =======================================================================
extern "C" void kernel_launch(void* const* d_in, const int* in_sizes, int n_in,
                              void* d_out, int out_size)
{
    (void)in_sizes; (void)n_in; (void)out_size;
    const float* x     = (const float*)d_in[0];
    const float* wq_a  = (const float*)d_in[1];
    const float* qnw   = (const float*)d_in[2];
    const float* wq_b  = (const float*)d_in[3];
    const float* wkv_a = (const float*)d_in[4];
    const float* kvnw  = (const float*)d_in[5];
    const float* wkv_b = (const float*)d_in[6];
    const float* wo    = (const float*)d_in[7];
    const float* kvc   = (const float*)d_in[8];
    const float* pec   = (const float*)d_in[9];
    const float* fc    = (const float*)d_in[10];
    const float* fs    = (const float*)d_in[11];
    float* out = (float*)d_out;

    // prologue: projections + q finalize (all before attention groups)
    k_sgemm_xqa<<<dim3(D_QL / BN, 2, 16), 256>>>(x, wq_a);
    k_red_t1<<<(N_TOK * D_QL + 255) / 256, 256>>>();
    k_rms_q<<<N_TOK, 256>>>(qnw);
    k_sgemm_qb<<<dim3(D_QB / BN, 2, 12), 256>>>(wq_b);
    k_red_q<<<(N_TOK * D_QB + 255) / 256, 256>>>();
    k_sgemm_kva<<<dim3((KVPE + BN - 1) / BN, 2, 16), 256>>>(x, wkv_a);
    k_red_kvf<<<(N_TOK * KVPE + 255) / 256, 256>>>();
    k_kvprep<<<N_TOK, 128>>>(kvnw, fc, fs);
    k_absorb<<<dim3(D_KVL / BN, 2, N_H), 256>>>(wkv_b);
    k_qrope<<<256, 256>>>(fc, fs);
    k_qsplit<<<(N_B * 64 * KVPE + 255) / 256, 256>>>();

    // attention: L2-resident batch groups (cvt -> scores -> attnout per group)
    const int cvt_blocks = (BGRP * T_MAX * (KVPE / 8) + 255) / 256;
    for (int b0 = 0; b0 < N_B; b0 += BGRP) {
        k_cvt<<<cvt_blocks, 256>>>(kvc, pec, b0);
        k_scores2<<<dim3(T_MAX / 128, BGRP), 256>>>(b0);
        k_attnout2<<<dim3(2, NSPLIT, BGRP), 256>>>(b0);
    }

    // epilogue
    k_lred<<<N_B, 64>>>();
    k_attnred<<<(N_B * 64 * D_KVL + 255) / 256, 256>>>();
    k_projv<<<dim3(4, 2, N_H), 256>>>(wkv_b);
    k_red_o<<<(N_TOK * 2048 + 255) / 256, 256>>>();
    k_sgemm_wo<<<dim3(2048 / BN, 2, 16), 256>>>(wo);
    k_red_out<<<(N_TOK * 2048 + 255) / 256, 256>>>(out);
}